// round 17
// baseline (speedup 1.0000x reference)
#include <cuda_runtime.h>
#include <math.h>

// Problem dims
#define H   256
#define H2  512
#define B   64
#define L   2048
#define V   32000
#define NG  4               // kA: groups per b
#define NCHG 16             // kA: chunks per group (32 l each)
#define NB7V 250            // k7: v tiles
#define VT7 128             // k7: v per tile
#define KH  256             // k7: k per half
#define KCH 16              // k7: k per W chunk
#define NCH7 16             // k7: chunks per half
#define WP7 17
#define WBUF7 (128 * 17)    // 2176 floats (single buffer)

typedef unsigned long long ull;

// ---------------- scratch (device globals) ----------------------------------------
__device__ __align__(16) float g_w2p[8][H2];
__device__ __align__(16) float g_w2[H2];
__device__ float g_bias;
__device__ __align__(16) float g_ehb[B];
__device__ __align__(16) float g_attn[B * L];        // exp(energy), unnormalized
__device__ __align__(16) float g_ps[B * NG];         // group exp-sums
__device__ __align__(16) float g_ctxp[B * NG * H];   // unnormalized partial ctx
__device__ __align__(16) float g_xT[H2 * B];         // [emb; ctx] transposed [k][b]
__device__ __align__(16) float g_hT[H * B];          // hidden transposed [k][b]
__device__ __align__(16) float g_yT[H2 * B];         // [h_new; ctx] transposed [k][b]
__device__ __align__(16) float g_part[500 * VT7 * B]; // k7 half-partials (16MB)
__device__ __align__(16) float g_logits[B * V];
__device__ __align__(16) float g_lpm[B * 256];
__device__ __align__(16) float g_lps[B * 256];
__device__ __align__(16) float g_lse[B];
__device__ int g_cnt0;
__device__ int g_cntA[B];
__device__ int g_cntV[NB7V];
__device__ int g_cnt7;

__device__ __forceinline__ ull fma2(ull a, ull x, ull c) {
    asm("fma.rn.f32x2 %0, %1, %2, %3;" : "=l"(a) : "l"(x), "l"(c), "l"(a));
    return a;
}
__device__ __forceinline__ ull pack2(float w) {
    ull r;
    asm("mov.b64 %0, {%1, %1};" : "=l"(r) : "f"(w));
    return r;
}
__device__ __forceinline__ float lo32(ull a) { return __uint_as_float((unsigned)(a & 0xffffffffull)); }
__device__ __forceinline__ float hi32(ull a) { return __uint_as_float((unsigned)(a >> 32)); }
__device__ __forceinline__ void cpasync16(unsigned smem, const void* g) {
    asm volatile("cp.async.ca.shared.global [%0], [%1], 16;" :: "r"(smem), "l"(g));
}
__device__ __forceinline__ void cpasync4(unsigned smem, const void* g) {
    asm volatile("cp.async.ca.shared.global [%0], [%1], 4;" :: "r"(smem), "l"(g));
}
#define CP_COMMIT() asm volatile("cp.async.commit_group;")
#define CP_WAIT0()  asm volatile("cp.async.wait_group 0;")

// ---------------- K0: w2 partials + bias + transposes + last-block combine --------
__global__ void k0_prep(const float* __restrict__ attn_W,
                        const float* __restrict__ attn_b,
                        const float* __restrict__ flatten,
                        const float* __restrict__ hidden,
                        const int*   __restrict__ input,
                        const float* __restrict__ emb_table)
{
    __shared__ float s_f[32];
    __shared__ float red[512];
    __shared__ float s_wh[H];
    __shared__ int s_last;
    int blk = blockIdx.x, tid = threadIdx.x;    // 512 threads, 9 blocks

    if (blk < 8) {
        if (tid < 32) s_f[tid] = flatten[blk * 32 + tid];
        __syncthreads();
        float acc = 0.f;
        #pragma unroll 8
        for (int i = 0; i < 32; i++)
            acc += attn_W[(size_t)(blk * 32 + i) * H2 + tid] * s_f[i];
        g_w2p[blk][tid] = acc;
    } else {
        red[tid] = (tid < H) ? flatten[tid] * attn_b[tid] : 0.f;
        __syncthreads();
        for (int s = 256; s > 0; s >>= 1) {
            if (tid < s) red[tid] += red[tid + s];
            __syncthreads();
        }
        if (tid == 0) g_bias = red[0];
        if (tid == 1) g_cnt7 = 0;
        if (tid >= 64 && tid < 128) g_cntA[tid - 64] = 0;
        if (tid >= 128 && tid < 128 + NB7V) g_cntV[tid - 128] = 0;
        for (int idx = tid; idx < B * H; idx += 512) {
            int b = idx >> 8, j = idx & 255;
            g_xT[j * B + b] = emb_table[(size_t)input[b] * H + j];
            g_hT[j * B + b] = hidden[idx];
        }
    }

    __threadfence();
    __syncthreads();
    if (tid == 0) s_last = (atomicAdd(&g_cnt0, 1) == 8) ? 1 : 0;
    __syncthreads();
    if (!s_last) return;

    float w = 0.f;
    #pragma unroll
    for (int k = 0; k < 8; k++) w += g_w2p[k][tid];
    g_w2[tid] = w;
    if (tid < H) s_wh[tid] = w;
    __syncthreads();

    int wid = tid >> 5, lane = tid & 31;        // 16 warps x 4 b
    float bias = g_bias;
    #pragma unroll
    for (int i = 0; i < 4; i++) {
        int b = wid * 4 + i;
        float a = 0.f;
        #pragma unroll
        for (int c = 0; c < 8; c++) {
            int k = c * 32 + lane;
            a += hidden[b * H + k] * s_wh[k];
        }
        #pragma unroll
        for (int o = 16; o > 0; o >>= 1) a += __shfl_down_sync(0xffffffffu, a, o);
        if (lane == 0) g_ehb[b] = a + bias;
    }
    if (tid == 0) g_cnt0 = 0;                   // reset for graph replay
}

// ---------------- KA-v4: energies + exp (no max shift; |e| bounded) + ctx ---------
// 256 blocks (b x 4 groups), 16 chunks of 32 l each, double-buffered cp.async.
__global__ __launch_bounds__(256) void kA_attn(const float* __restrict__ enc,
                                               float* __restrict__ out_attn)
{
    extern __shared__ float sm[];
    float* s_w2 = sm + 16384;        // 256
    float* s_w  = s_w2 + H;          // 32 (chunk exp weights)
    float* s_iv = s_w + 32;          // [0]=inv
    int*   s_fl = (int*)(s_iv + 2);

    int b = blockIdx.x >> 2;
    int g = blockIdx.x & 3;
    int tid = threadIdx.x;
    int wid = tid >> 5, lane = tid & 31;

    unsigned tb = (unsigned)__cvta_generic_to_shared(sm);
    const float4* src0 = (const float4*)(enc + (size_t)b * H);

    // prologue: chunk 0 into buf 0
    {
        int l0 = g * (NCHG * 32);
        #pragma unroll
        for (int i = 0; i < 8; i++) {
            int idx = tid + 256 * i;
            int row = idx >> 6, col = idx & 63;
            cpasync16(tb + (unsigned)idx * 16, src0 + (size_t)(l0 + row) * 4096 + col);
        }
        CP_COMMIT();
    }
    s_w2[tid] = g_w2[H + tid];
    float ehb = g_ehb[b];
    float ctx_acc = 0.f;
    float s_run = 0.f;                          // warp 0 lanes: partial sums

    for (int i = 0; i < NCHG; i++) {
        CP_WAIT0();
        __syncthreads();
        if (i + 1 < NCHG) {
            int l0 = g * (NCHG * 32) + (i + 1) * 32;
            unsigned dst = tb + (unsigned)(((i + 1) & 1) * 8192) * 4;
            #pragma unroll
            for (int t = 0; t < 8; t++) {
                int idx = tid + 256 * t;
                int row = idx >> 6, col = idx & 63;
                cpasync16(dst + (unsigned)idx * 16, src0 + (size_t)(l0 + row) * 4096 + col);
            }
            CP_COMMIT();
        }

        float* tile = sm + (i & 1) * 8192;
        int l0 = g * (NCHG * 32) + i * 32;

        #pragma unroll
        for (int r = 0; r < 4; r++) {
            int l = wid * 4 + r;
            const float4* tr = (const float4*)(tile + l * H);
            const float4* w4 = (const float4*)s_w2;
            float4 t0 = tr[lane],      w0 = w4[lane];
            float4 t1 = tr[32 + lane], w1 = w4[32 + lane];
            float a = t0.x * w0.x + t0.y * w0.y + t0.z * w0.z + t0.w * w0.w
                    + t1.x * w1.x + t1.y * w1.y + t1.z * w1.z + t1.w * w1.w;
            #pragma unroll
            for (int o = 16; o > 0; o >>= 1) a += __shfl_down_sync(0xffffffffu, a, o);
            if (lane == 0) {
                float w = __expf(a + ehb);
                s_w[l] = w;
                g_attn[b * L + l0 + l] = w;
            }
        }
        __syncthreads();

        if (wid == 0) s_run += s_w[lane];

        float a0 = 0.f, a1 = 0.f, a2 = 0.f, a3 = 0.f;
        #pragma unroll
        for (int l = 0; l < 32; l += 4) {
            a0 += s_w[l + 0] * tile[(l + 0) * H + tid];
            a1 += s_w[l + 1] * tile[(l + 1) * H + tid];
            a2 += s_w[l + 2] * tile[(l + 2) * H + tid];
            a3 += s_w[l + 3] * tile[(l + 3) * H + tid];
        }
        ctx_acc += (a0 + a1) + (a2 + a3);
    }

    g_ctxp[(size_t)(b * NG + g) * H + tid] = ctx_acc;
    if (wid == 0) {
        #pragma unroll
        for (int o = 16; o > 0; o >>= 1) s_run += __shfl_xor_sync(0xffffffffu, s_run, o);
        if (lane == 0) g_ps[b * NG + g] = s_run;
    }

    __threadfence();
    __syncthreads();
    if (tid == 0) s_fl[0] = (atomicAdd(&g_cntA[b], 1) == NG - 1) ? 1 : 0;
    __syncthreads();
    if (!s_fl[0]) return;

    if (tid == 0) {
        float ssum = 0.f;
        #pragma unroll
        for (int gg = 0; gg < NG; gg++) ssum += g_ps[b * NG + gg];
        s_iv[0] = 1.f / ssum;
    }
    __syncthreads();
    float inv = s_iv[0];

    float acc = 0.f;
    #pragma unroll
    for (int gg = 0; gg < NG; gg++)
        acc += g_ctxp[(size_t)(b * NG + gg) * H + tid];
    float ctxv = acc * inv;
    g_xT[(H + tid) * B + b] = ctxv;
    g_yT[(H + tid) * B + b] = ctxv;

    if (out_attn)
        for (int l = tid; l < L; l += 256)
            out_attn[b * L + l] = g_attn[b * L + l] * inv;
}

// ---------------- K56: GRU, block per j, 8 warps split k, lanes = b-pairs ---------
__global__ __launch_bounds__(256) void k56_gru(const float* __restrict__ Wih,
                                               const float* __restrict__ Whh,
                                               const float* __restrict__ bih,
                                               const float* __restrict__ bhh,
                                               float* __restrict__ out_h)
{
    __shared__ float s_px[8][3][64];            // warp, gate, b
    int j = blockIdx.x;                         // 0..255
    int tid = threadIdx.x;
    int wid = tid >> 5, lane = tid & 31;

    ull ar = 0, az = 0, an = 0;
    if (wid < 4) {
        int k0 = wid * 128;
        const float* wr = Wih + (size_t)j * H2 + k0;
        const float* wz = Wih + (size_t)(j + H) * H2 + k0;
        const float* wn = Wih + (size_t)(j + 2 * H) * H2 + k0;
        const float* xp = g_xT + k0 * B + lane * 2;
        #pragma unroll 8
        for (int k = 0; k < 128; k++) {
            ull x2 = *(const ull*)(xp + k * B);
            ar = fma2(ar, pack2(wr[k]), x2);
            az = fma2(az, pack2(wz[k]), x2);
            an = fma2(an, pack2(wn[k]), x2);
        }
    } else {
        int k0 = (wid - 4) * 64;
        const float* wr = Whh + (size_t)j * H + k0;
        const float* wz = Whh + (size_t)(j + H) * H + k0;
        const float* wn = Whh + (size_t)(j + 2 * H) * H + k0;
        const float* hp = g_hT + k0 * B + lane * 2;
        #pragma unroll 8
        for (int k = 0; k < 64; k++) {
            ull h2 = *(const ull*)(hp + k * B);
            ar = fma2(ar, pack2(wr[k]), h2);
            az = fma2(az, pack2(wz[k]), h2);
            an = fma2(an, pack2(wn[k]), h2);
        }
    }
    s_px[wid][0][lane * 2] = lo32(ar); s_px[wid][0][lane * 2 + 1] = hi32(ar);
    s_px[wid][1][lane * 2] = lo32(az); s_px[wid][1][lane * 2 + 1] = hi32(az);
    s_px[wid][2][lane * 2] = lo32(an); s_px[wid][2][lane * 2 + 1] = hi32(an);
    __syncthreads();

    if (wid != 0) return;
    float bir = bih[j], biz = bih[j + H], bin = bih[j + 2 * H];
    float bhr = bhh[j], bhz = bhh[j + H], bhn = bhh[j + 2 * H];
    float2 hp2 = *(const float2*)(g_hT + j * B + lane * 2);

    float hn_out[2];
    #pragma unroll
    for (int d = 0; d < 2; d++) {
        int bb = lane * 2 + d;
        float gir = s_px[0][0][bb] + s_px[1][0][bb] + s_px[2][0][bb] + s_px[3][0][bb] + bir;
        float giz = s_px[0][1][bb] + s_px[1][1][bb] + s_px[2][1][bb] + s_px[3][1][bb] + biz;
        float gin = s_px[0][2][bb] + s_px[1][2][bb] + s_px[2][2][bb] + s_px[3][2][bb] + bin;
        float ghr = s_px[4][0][bb] + s_px[5][0][bb] + s_px[6][0][bb] + s_px[7][0][bb] + bhr;
        float ghz = s_px[4][1][bb] + s_px[5][1][bb] + s_px[6][1][bb] + s_px[7][1][bb] + bhz;
        float ghn = s_px[4][2][bb] + s_px[5][2][bb] + s_px[6][2][bb] + s_px[7][2][bb] + bhn;
        float r = 1.f / (1.f + __expf(-(gir + ghr)));
        float z = 1.f / (1.f + __expf(-(giz + ghz)));
        float n = tanhf(gin + r * ghn);
        float hprev = d ? hp2.y : hp2.x;
        hn_out[d] = (1.f - z) * n + z * hprev;
    }
    *(float2*)(g_yT + j * B + lane * 2) = make_float2(hn_out[0], hn_out[1]);
    if (out_h) {
        out_h[(lane * 2 + 0) * H + j] = hn_out[0];
        out_h[(lane * 2 + 1) * H + j] = hn_out[1];
    }
}

// ---------------- K7-v10: logits GEMM, 128v x 64b, k-split x2, 3 blocks/SM --------
// Grid 500 = 250 v-tiles x 2 k-halves; 256 threads; y half resident (64KB,
// swizzled), W single-buffered (8.7KB) -> smem 74.2KB, 3 blocks/SM (24 warps).
// W-load stalls absorbed by the other resident blocks; partial traffic halved.
#define SOP7 129
__global__ __launch_bounds__(256, 3) void k7_logits(const float* __restrict__ outW,
                                                    const float* __restrict__ outb)
{
    extern __shared__ float sm[];
    float* s_y = sm;                             // 16384 floats (64KB), swizzled
    float* s_w = sm + 16384;                     // 2176 floats (8.7KB), single buf
    int tid = threadIdx.x;
    int vt = blockIdx.x >> 1;
    int half = blockIdx.x & 1;
    int v0b = vt * VT7;
    int kb = half * KH;

    unsigned syb = (unsigned)__cvta_generic_to_shared(s_y);
    unsigned swb = (unsigned)__cvta_generic_to_shared(s_w);

    // W chunk staging: 2048 scalars (128 rows x 16 k), 8/thread
    #define K7_ISSUE_W(cc) do {                                                  \
        int _c = (cc);                                                           \
        _Pragma("unroll")                                                        \
        for (int t = 0; t < 8; t++) {                                            \
            int idx = tid + 256 * t;                                             \
            int row = idx >> 4, kk = idx & 15;                                   \
            cpasync4(swb + (unsigned)(row * WP7 + kk) * 4,                       \
                     outW + (size_t)(v0b + row) * H2 + kb + _c * KCH + kk);      \
        }                                                                        \
    } while (0)

    // prologue: y half (4096 f4, swizzled, 16/thread) + W chunk 0
    #pragma unroll
    for (int t = 0; t < 16; t++) {
        int idx = tid + 256 * t;                 // f4 index
        int k = idx >> 4, f4 = idx & 15;
        int swz = (f4 & 14) | ((f4 ^ (f4 >> 3)) & 1);
        cpasync16(syb + (unsigned)(k * 16 + swz) * 16,
                  g_yT + (size_t)(kb + k) * 64 + f4 * 4);
    }
    K7_ISSUE_W(0);
    CP_COMMIT();
    CP_WAIT0();
    __syncthreads();

    int bg = tid & 7;                            // 8 b-groups of 8
    int tv = tid >> 3;                           // 32 v-groups of 4 -> 128 v
    int vl = tv * 4;
    int b0 = bg * 8;
    int sw = (bg >> 2) & 1;
    int offA = sw * 4, offB = 4 - offA;

    ull acc[4][4];
    #pragma unroll
    for (int i = 0; i < 4; i++)
        #pragma unroll
        for (int p = 0; p < 4; p++) acc[i][p] = 0ull;

    for (int c = 0; c < NCH7; c++) {
        #pragma unroll 4
        for (int kk = 0; kk < KCH; kk++) {
            int k = c * KCH + kk;
            const float* yr = s_y + k * 64 + b0;
            ulonglong2 ta = *(const ulonglong2*)(yr + offA);
            ulonglong2 tc = *(const ulonglong2*)(yr + offB);
            #pragma unroll
            for (int i = 0; i < 4; i++) {
                ull w2 = pack2(s_w[(vl + i) * WP7 + kk]);
                acc[i][0] = fma2(acc[i][0], w2, ta.x);
                acc[i][1] = fma2(acc[i][1], w2, ta.y);
                acc[i][2] = fma2(acc[i][2], w2, tc.x);
                acc[i][3] = fma2(acc[i][3], w2, tc.y);
            }
        }
        if (c + 1 < NCH7) {
            __syncthreads();                     // all done reading W chunk c
            K7_ISSUE_W(c + 1);
            CP_COMMIT();
            CP_WAIT0();
            __syncthreads();                     // W chunk c+1 visible to all
        }
    }
    __syncthreads();

    // stage partial 64b x 128v (pitch 129)
    float* s_out = sm;                           // 8256 <= 18560 floats
    #pragma unroll
    for (int i = 0; i < 4; i++) {
        int v = vl + i;
        #pragma unroll
        for (int p = 0; p < 4; p++) {
            s_out[(b0 + 2 * p + 0) * SOP7 + v] = lo32(acc[i][p]);
            s_out[(b0 + 2 * p + 1) * SOP7 + v] = hi32(acc[i][p]);
        }
    }
    __syncthreads();

    // coalesced partial write: g_part[blk][b][v], 2048 f4, 8/thread
    float4* gp = (float4*)(g_part + (size_t)blockIdx.x * (VT7 * B));
    #pragma unroll
    for (int t = 0; t < 8; t++) {
        int i = tid + 256 * t;
        int v4 = i & 31, b = i >> 5;
        const float* s = s_out + b * SOP7 + v4 * 4;
        gp[i] = make_float4(s[0], s[1], s[2], s[3]);
    }

    // per-v-tile finisher (last half): sum 2 partials + bias -> logits, lse
    __shared__ int s_last;
    __threadfence();
    __syncthreads();
    if (tid == 0) s_last = (atomicAdd(&g_cntV[vt], 1) == 1) ? 1 : 0;
    __syncthreads();
    if (!s_last) return;

    const float4* p0 = (const float4*)(g_part + (size_t)(vt * 2 + 0) * (VT7 * B));
    const float4* p1 = (const float4*)(g_part + (size_t)(vt * 2 + 1) * (VT7 * B));
    #pragma unroll
    for (int t = 0; t < 8; t++) {
        int i = tid + 256 * t;
        int v4 = i & 31, b = i >> 5;
        float4 a = p0[i], c = p1[i];
        float4 bi = *(const float4*)(outb + v0b + v4 * 4);
        float4 r = make_float4(a.x + c.x + bi.x, a.y + c.y + bi.y,
                               a.z + c.z + bi.z, a.w + c.w + bi.w);
        *(float4*)(g_logits + (size_t)b * V + v0b + v4 * 4) = r;
        float* s = s_out + b * SOP7 + v4 * 4;
        s[0] = r.x; s[1] = r.y; s[2] = r.z; s[3] = r.w;
    }
    __syncthreads();

    // lse partials: 4 threads per b, 32 v each
    int bq = tid >> 2, i4 = tid & 3;
    {
        const float* rr = s_out + bq * SOP7 + i4 * 32;
        float m = -INFINITY;
        #pragma unroll
        for (int j = 0; j < 32; j++) m = fmaxf(m, rr[j]);
        m = fmaxf(m, __shfl_xor_sync(0xffffffffu, m, 1));
        m = fmaxf(m, __shfl_xor_sync(0xffffffffu, m, 2));
        float s = 0.f;
        #pragma unroll
        for (int j = 0; j < 32; j++) s += __expf(rr[j] - m);
        s += __shfl_xor_sync(0xffffffffu, s, 1);
        s += __shfl_xor_sync(0xffffffffu, s, 2);
        if (i4 == 0) {
            g_lpm[bq * 256 + vt] = m;
            g_lps[bq * 256 + vt] = s;
        }
    }

    // last finisher merges lse
    __shared__ int s_fin;
    __threadfence();
    __syncthreads();
    if (tid == 0) s_fin = (atomicAdd(&g_cnt7, 1) == NB7V - 1) ? 1 : 0;
    __syncthreads();
    if (!s_fin) return;

    float m = -INFINITY;
    for (int i = i4; i < NB7V; i += 4) m = fmaxf(m, g_lpm[bq * 256 + i]);
    m = fmaxf(m, __shfl_xor_sync(0xffffffffu, m, 1));
    m = fmaxf(m, __shfl_xor_sync(0xffffffffu, m, 2));
    float s = 0.f;
    for (int i = i4; i < NB7V; i += 4)
        s += g_lps[bq * 256 + i] * __expf(g_lpm[bq * 256 + i] - m);
    s += __shfl_xor_sync(0xffffffffu, s, 1);
    s += __shfl_xor_sync(0xffffffffu, s, 2);
    if (i4 == 0) g_lse[bq] = m + logf(s);
}

// ---------------- K8w: out = logits - lse[b] ---------------------------------------
__global__ void k8w_write(float* __restrict__ out)
{
    int idx = blockIdx.x * 256 + threadIdx.x;   // float4 index
    int b = idx / (V / 4);
    float lse = g_lse[b];
    float4 v = ((const float4*)g_logits)[idx];
    v.x -= lse; v.y -= lse; v.z -= lse; v.w -= lse;
    ((float4*)out)[idx] = v;
}

// ---------------- host launch ------------------------------------------------------
extern "C" void kernel_launch(void* const* d_in, const int* in_sizes, int n_in,
                              void* d_out, int out_size)
{
    int s = (n_in >= 14 && in_sizes[3] == 1) ? 0 : -1;
    const int*   input    = (const int*)  d_in[0];
    const float* hidden   = (const float*)d_in[1];
    const float* enc      = (const float*)d_in[2];
    const float* emb      = (const float*)d_in[4 + s];
    const float* attn_W   = (const float*)d_in[5 + s];
    const float* attn_b   = (const float*)d_in[6 + s];
    const float* flatten  = (const float*)d_in[7 + s];
    const float* Wih      = (const float*)d_in[8 + s];
    const float* Whh      = (const float*)d_in[9 + s];
    const float* bih      = (const float*)d_in[10 + s];
    const float* bhh      = (const float*)d_in[11 + s];
    const float* outW     = (const float*)d_in[12 + s];
    const float* outb     = (const float*)d_in[13 + s];

    float* dout     = (float*)d_out;
    float* out_h    = (out_size >= B * V + B * H) ? dout + B * V : nullptr;
    float* out_attn = (out_size >= B * V + B * H + B * L) ? dout + B * V + B * H : nullptr;

    k0_prep<<<9, 512>>>(attn_W, attn_b, flatten, hidden, input, emb);

    int smem_kA = (16384 + 256 + 32 + 2 + 4) * (int)sizeof(float);    // ~66.7KB
    cudaFuncSetAttribute(kA_attn, cudaFuncAttributeMaxDynamicSharedMemorySize, smem_kA);
    kA_attn<<<B * NG, 256, smem_kA>>>(enc, out_attn);

    k56_gru<<<256, 256>>>(Wih, Whh, bih, bhh, out_h);

    int smem_k7 = (16384 + WBUF7) * (int)sizeof(float);               // 74240 B
    cudaFuncSetAttribute(k7_logits, cudaFuncAttributeMaxDynamicSharedMemorySize, smem_k7);
    k7_logits<<<NB7V * 2, 256, smem_k7>>>(outW, outb);

    k8w_write<<<(B * V / 4) / 256, 256>>>(dout);
}